// round 1
// baseline (speedup 1.0000x reference)
#include <cuda_runtime.h>
#include <cuda_bf16.h>
#include <stdint.h>

// Fixed problem shape (registry problem is fixed-shape; buffers sized statically).
#define N_MAX 50000
#define E_MAX 800000
#define DH 64

// ---------------- device scratch (static globals: no allocation allowed) -----
__device__ __align__(256) float g_bufA[N_MAX * DH];   // xw  (per-layer GEMM output)
__device__ __align__(256) float g_bufB[N_MAX * DH];   // agg (per-layer aggregate output / next input)
__device__ __align__(16)  float g_deg[N_MAX];
__device__ __align__(16)  float g_dis[N_MAX];
__device__ __align__(16)  int   g_src[E_MAX];
__device__ __align__(16)  int   g_dst[E_MAX];
__device__ __align__(16)  float g_enorm[E_MAX];
__device__ int g_is64;

// ---------------- edge_index dtype detection --------------------------------
// int64 little-endian with values < 2^31 => every odd int32 word is 0.
__global__ void k_detect(const int* __restrict__ w) {
    int allz = 1;
#pragma unroll
    for (int i = 1; i < 64; i += 2) allz &= (w[i] == 0);
    g_is64 = allz;
}

__global__ void k_extract(const void* __restrict__ ei, int E) {
    int e = blockIdx.x * blockDim.x + threadIdx.x;
    if (e >= E) return;
    int s, d;
    if (g_is64) {
        const long long* p = (const long long*)ei;
        s = (int)p[e];
        d = (int)p[e + E];
    } else {
        const int* p = (const int*)ei;
        s = p[e];
        d = p[e + E];
    }
    g_src[e] = s;
    g_dst[e] = d;
}

// ---------------- degree / norm ----------------------------------------------
__global__ void k_deg_init(int n) {
    int i = blockIdx.x * blockDim.x + threadIdx.x;
    if (i < n) g_deg[i] = 1.0f;   // self-loop
}

__global__ void k_deg_count(int E) {
    int e = blockIdx.x * blockDim.x + threadIdx.x;
    if (e < E) atomicAdd(&g_deg[g_dst[e]], 1.0f);
}

__global__ void k_dis(int n) {
    int i = blockIdx.x * blockDim.x + threadIdx.x;
    if (i < n) g_dis[i] = rsqrtf(g_deg[i]);
}

__global__ void k_enorm(int E) {
    int e = blockIdx.x * blockDim.x + threadIdx.x;
    if (e < E) g_enorm[e] = g_dis[g_src[e]] * g_dis[g_dst[e]];
}

// ---------------- GEMM: out[n,64] = f(in[n,:]) @ W  (W is 64x64 row-major) ---
// f(v) = relu(v + bias_in[k]) when RELU (bias/relu of the PREVIOUS layer fused
// into this layer's input read). 4 threads per node, 16 output cols each.
template <bool RELU, bool FROM_BUFB>
__global__ __launch_bounds__(256) void k_gemm64(
    const float* __restrict__ in, const float* __restrict__ W,
    const float* __restrict__ bias_in, int n)
{
    __shared__ float Ws[64 * 64];
    __shared__ float bs[64];
    int tid = threadIdx.x;
#pragma unroll
    for (int i = tid; i < 64 * 64 / 4; i += 256)
        ((float4*)Ws)[i] = ((const float4*)W)[i];
    if (RELU && tid < 16) ((float4*)bs)[tid] = ((const float4*)bias_in)[tid];
    __syncthreads();

    int node = blockIdx.x * 64 + (tid >> 2);
    int quad = tid & 3;
    if (node >= n) return;

    const float* src = FROM_BUFB ? (g_bufB + (size_t)node * 64)
                                 : (in + (size_t)node * 64);
    float acc[16];
#pragma unroll
    for (int j = 0; j < 16; j++) acc[j] = 0.f;

    const float4* xr4 = (const float4*)src;
    for (int k4 = 0; k4 < 16; k4++) {
        float4 v4 = xr4[k4];
        float vv[4] = {v4.x, v4.y, v4.z, v4.w};
#pragma unroll
        for (int u = 0; u < 4; u++) {
            int k = k4 * 4 + u;
            float v = vv[u];
            if (RELU) v = fmaxf(v + bs[k], 0.f);
            const float* wrow = &Ws[k * 64 + quad * 16];
#pragma unroll
            for (int j = 0; j < 16; j++) acc[j] = fmaf(v, wrow[j], acc[j]);
        }
    }
    float* op = g_bufA + (size_t)node * 64 + quad * 16;
#pragma unroll
    for (int j = 0; j < 16; j += 4)
        *(float4*)(op + j) = make_float4(acc[j], acc[j + 1], acc[j + 2], acc[j + 3]);
}

// ---------------- self-loop init: agg[i] = xw[i] * dis[node]^2 ---------------
__global__ __launch_bounds__(256) void k_selfloop(int n) {
    int i = blockIdx.x * blockDim.x + threadIdx.x;   // over n*16 float4s
    if (i >= n * 16) return;
    int node = i >> 4;
    float d = g_dis[node];
    float s = d * d;
    float4 v = ((const float4*)g_bufA)[i];
    ((float4*)g_bufB)[i] = make_float4(v.x * s, v.y * s, v.z * s, v.w * s);
}

// ---------------- edge scatter: agg[dst] += xw[src] * norm -------------------
// One float4 column per thread; 16 consecutive threads = one edge (coalesced
// 256B row gather). Vector atomics via red.global.add.v4.f32 (sm_90+).
__global__ __launch_bounds__(256) void k_scatter(int E) {
    int i = blockIdx.x * blockDim.x + threadIdx.x;
    int e = i >> 4;
    int c = i & 15;
    if (e >= E) return;
    int s = g_src[e];
    int d = g_dst[e];
    float nrm = g_enorm[e];
    float4 v = ((const float4*)(g_bufA + (size_t)s * 64))[c];
    float4* addr = ((float4*)(g_bufB + (size_t)d * 64)) + c;
    asm volatile("red.global.add.v4.f32 [%0], {%1,%2,%3,%4};"
                 :: "l"(addr),
                    "f"(v.x * nrm), "f"(v.y * nrm), "f"(v.z * nrm), "f"(v.w * nrm)
                 : "memory");
}

// ---------------- final linear: out = relu(agg2 + b2) @ linW + linb ----------
__global__ __launch_bounds__(256) void k_final(
    const float* __restrict__ linW, const float* __restrict__ b2,
    const float* __restrict__ linb, float* __restrict__ out, int n)
{
    __shared__ float Ws[64 * 8];
    __shared__ float bs[64];
    __shared__ float lb[8];
    int tid = threadIdx.x;
#pragma unroll
    for (int i = tid; i < 128; i += 256) ((float4*)Ws)[i] = ((const float4*)linW)[i];
    if (tid < 16) ((float4*)bs)[tid] = ((const float4*)b2)[tid];
    if (tid < 2)  ((float4*)lb)[tid] = ((const float4*)linb)[tid];
    __syncthreads();

    int node = blockIdx.x * blockDim.x + tid;
    if (node >= n) return;

    float acc[8];
#pragma unroll
    for (int j = 0; j < 8; j++) acc[j] = lb[j];

    const float* xr = g_bufB + (size_t)node * 64;
    for (int k = 0; k < 64; k++) {
        float v = fmaxf(xr[k] + bs[k], 0.f);
        const float* wrow = &Ws[k * 8];
#pragma unroll
        for (int j = 0; j < 8; j++) acc[j] = fmaf(v, wrow[j], acc[j]);
    }
    float* op = out + (size_t)node * 8;
#pragma unroll
    for (int j = 0; j < 8; j += 4)
        *(float4*)(op + j) = make_float4(acc[j], acc[j + 1], acc[j + 2], acc[j + 3]);
}

// ---------------- host launcher ----------------------------------------------
extern "C" void kernel_launch(void* const* d_in, const int* in_sizes, int n_in,
                              void* d_out, int out_size)
{
    const float* x    = (const float*)d_in[0];
    const void*  ei   = d_in[1];
    const float* W0   = (const float*)d_in[2];
    const float* b0   = (const float*)d_in[3];
    const float* W1   = (const float*)d_in[4];
    const float* b1   = (const float*)d_in[5];
    const float* W2   = (const float*)d_in[6];
    const float* b2   = (const float*)d_in[7];
    const float* linW = (const float*)d_in[8];
    const float* linb = (const float*)d_in[9];
    float* out = (float*)d_out;

    int N = in_sizes[0] / DH;       // 50000
    int E = in_sizes[1] / 2;        // 800000

    const int T = 256;
    int gN  = (N + T - 1) / T;
    int gE  = (E + T - 1) / T;
    int gN16 = (N * 16 + T - 1) / T;
    int gE16 = (E * 16 + T - 1) / T;
    int gG  = (N + 63) / 64;

    // preprocessing (norms reused by all 3 layers)
    k_detect<<<1, 1>>>((const int*)ei);
    k_extract<<<gE, T>>>(ei, E);
    k_deg_init<<<gN, T>>>(N);
    k_deg_count<<<gE, T>>>(E);
    k_dis<<<gN, T>>>(N);
    k_enorm<<<gE, T>>>(E);

    // layer 0: x @ W0 -> aggregate
    k_gemm64<false, false><<<gG, T>>>(x, W0, nullptr, N);
    k_selfloop<<<gN16, T>>>(N);
    k_scatter<<<gE16, T>>>(E);

    // layer 1: relu(agg0 + b0) @ W1 -> aggregate
    k_gemm64<true, true><<<gG, T>>>(nullptr, W1, b0, N);
    k_selfloop<<<gN16, T>>>(N);
    k_scatter<<<gE16, T>>>(E);

    // layer 2: relu(agg1 + b1) @ W2 -> aggregate
    k_gemm64<true, true><<<gG, T>>>(nullptr, W2, b1, N);
    k_selfloop<<<gN16, T>>>(N);
    k_scatter<<<gE16, T>>>(E);

    // head: relu(agg2 + b2) @ linW + linb
    k_final<<<gN, T>>>(linW, b2, linb, out, N);
}

// round 2
// speedup vs baseline: 1.1496x; 1.1496x over previous
#include <cuda_runtime.h>
#include <cuda_bf16.h>
#include <stdint.h>

#define N_MAX 50000
#define E_MAX 800000
#define DH 64
#define SCAN_B 256
#define NBLK ((N_MAX + SCAN_B - 1) / SCAN_B)   // 196

// ---------------- device scratch ---------------------------------------------
__device__ __align__(256) float g_bufA[N_MAX * DH];   // xw (GEMM out)
__device__ __align__(256) float g_bufB[N_MAX * DH];   // agg (gather out / next in)
__device__ __align__(16)  float g_dis[N_MAX];
__device__ __align__(16)  int   g_cnt[N_MAX];         // in-degree (no self loop)
__device__ __align__(16)  int   g_fill[N_MAX];
__device__ __align__(16)  int   g_rowptr[N_MAX + 1];
__device__ __align__(16)  int   g_bsum[NBLK];
__device__ __align__(16)  int   g_boff[NBLK];
__device__ __align__(16)  int   g_src[E_MAX];
__device__ __align__(16)  int   g_dst[E_MAX];
__device__ __align__(16)  int2  g_csr[E_MAX];         // (src, norm-as-int)
__device__ int g_is64;

// ---------------- edge dtype detect ------------------------------------------
__global__ void k_detect(const int* __restrict__ w) {
    int allz = 1;
#pragma unroll
    for (int i = 1; i < 64; i += 2) allz &= (w[i] == 0);
    g_is64 = allz;
}

__global__ void k_zero(int n) {
    int i = blockIdx.x * blockDim.x + threadIdx.x;
    if (i < n) g_cnt[i] = 0;
}

__global__ void k_extract(const void* __restrict__ ei, int E) {
    int e = blockIdx.x * blockDim.x + threadIdx.x;
    if (e >= E) return;
    int s, d;
    if (g_is64) {
        const long long* p = (const long long*)ei;
        s = (int)p[e];
        d = (int)p[e + E];
    } else {
        const int* p = (const int*)ei;
        s = p[e];
        d = p[e + E];
    }
    g_src[e] = s;
    g_dst[e] = d;
    atomicAdd(&g_cnt[d], 1);
}

// dis = rsqrt(deg) with deg = in-degree + self-loop; also zero fill counters.
__global__ void k_dis(int n) {
    int i = blockIdx.x * blockDim.x + threadIdx.x;
    if (i >= n) return;
    g_dis[i] = rsqrtf((float)(g_cnt[i] + 1));
    g_fill[i] = 0;
}

// ---------------- exclusive scan of g_cnt -> g_rowptr -------------------------
__global__ void k_scan1(int n) {
    __shared__ int s[SCAN_B];
    int t = threadIdx.x;
    int i = blockIdx.x * SCAN_B + t;
    int v = (i < n) ? g_cnt[i] : 0;
    s[t] = v;
    __syncthreads();
#pragma unroll
    for (int off = 1; off < SCAN_B; off <<= 1) {
        int add = (t >= off) ? s[t - off] : 0;
        __syncthreads();
        s[t] += add;
        __syncthreads();
    }
    if (i < n) g_rowptr[i] = s[t] - v;           // exclusive
    if (t == SCAN_B - 1) g_bsum[blockIdx.x] = s[t];
}

__global__ void k_scan2(int nblk) {
    __shared__ int s[SCAN_B];
    int t = threadIdx.x;
    int v = (t < nblk) ? g_bsum[t] : 0;
    s[t] = v;
    __syncthreads();
#pragma unroll
    for (int off = 1; off < SCAN_B; off <<= 1) {
        int add = (t >= off) ? s[t - off] : 0;
        __syncthreads();
        s[t] += add;
        __syncthreads();
    }
    if (t < nblk) g_boff[t] = s[t] - v;          // exclusive
}

__global__ void k_scan3(int n, int E) {
    int i = blockIdx.x * SCAN_B + threadIdx.x;
    if (i < n) g_rowptr[i] += g_boff[blockIdx.x];
    if (i == 0) g_rowptr[n] = E;
}

// ---------------- CSR fill -----------------------------------------------------
__global__ void k_fill(int E) {
    int e = blockIdx.x * blockDim.x + threadIdx.x;
    if (e >= E) return;
    int s = g_src[e];
    int d = g_dst[e];
    int pos = g_rowptr[d] + atomicAdd(&g_fill[d], 1);
    float nrm = g_dis[s] * g_dis[d];
    g_csr[pos] = make_int2(s, __float_as_int(nrm));
}

// ---------------- GEMM: g_bufA[n,64] = f(in[n,:]) @ W --------------------------
template <bool RELU, bool FROM_BUFB>
__global__ __launch_bounds__(256) void k_gemm64(
    const float* __restrict__ in, const float* __restrict__ W,
    const float* __restrict__ bias_in, int n)
{
    __shared__ float Ws[64 * 64];
    __shared__ float bs[64];
    int tid = threadIdx.x;
#pragma unroll
    for (int i = tid; i < 64 * 64 / 4; i += 256)
        ((float4*)Ws)[i] = ((const float4*)W)[i];
    if (RELU && tid < 16) ((float4*)bs)[tid] = ((const float4*)bias_in)[tid];
    __syncthreads();

    int node = blockIdx.x * 64 + (tid >> 2);
    int quad = tid & 3;
    if (node >= n) return;

    const float* src = FROM_BUFB ? (g_bufB + (size_t)node * 64)
                                 : (in + (size_t)node * 64);
    float acc[16];
#pragma unroll
    for (int j = 0; j < 16; j++) acc[j] = 0.f;

    const float4* xr4 = (const float4*)src;
    for (int k4 = 0; k4 < 16; k4++) {
        float4 v4 = xr4[k4];
        float vv[4] = {v4.x, v4.y, v4.z, v4.w};
#pragma unroll
        for (int u = 0; u < 4; u++) {
            int k = k4 * 4 + u;
            float v = vv[u];
            if (RELU) v = fmaxf(v + bs[k], 0.f);
            const float* wrow = &Ws[k * 64 + quad * 16];
#pragma unroll
            for (int j = 0; j < 16; j++) acc[j] = fmaf(v, wrow[j], acc[j]);
        }
    }
    float* op = g_bufA + (size_t)node * 64 + quad * 16;
#pragma unroll
    for (int j = 0; j < 16; j += 4)
        *(float4*)(op + j) = make_float4(acc[j], acc[j + 1], acc[j + 2], acc[j + 3]);
}

// ---------------- CSR gather: agg[v] = dis[v]^2*xw[v] + sum_nbr xw[s]*norm ----
// 16 threads per node, one float4 column each. Neighbor (src,norm) pairs are
// warp-broadcast int2 loads. No atomics. 2-wide unroll for intra-thread MLP.
__global__ __launch_bounds__(256) void k_gather(int n) {
    int tid = threadIdx.x;
    int node = blockIdx.x * 16 + (tid >> 4);
    int c = tid & 15;
    if (node >= n) return;

    float dv = g_dis[node];
    float sl = dv * dv;
    const float4* xa = (const float4*)g_bufA;
    float4 me = xa[node * 16 + c];
    float ax = me.x * sl, ay = me.y * sl, az = me.z * sl, aw = me.w * sl;

    int p   = g_rowptr[node];
    int end = g_rowptr[node + 1];

    for (; p + 1 < end; p += 2) {
        int2 e0 = g_csr[p];
        int2 e1 = g_csr[p + 1];
        float n0 = __int_as_float(e0.y);
        float n1 = __int_as_float(e1.y);
        float4 v0 = xa[e0.x * 16 + c];
        float4 v1 = xa[e1.x * 16 + c];
        ax = fmaf(v0.x, n0, ax); ay = fmaf(v0.y, n0, ay);
        az = fmaf(v0.z, n0, az); aw = fmaf(v0.w, n0, aw);
        ax = fmaf(v1.x, n1, ax); ay = fmaf(v1.y, n1, ay);
        az = fmaf(v1.z, n1, az); aw = fmaf(v1.w, n1, aw);
    }
    if (p < end) {
        int2 e0 = g_csr[p];
        float n0 = __int_as_float(e0.y);
        float4 v0 = xa[e0.x * 16 + c];
        ax = fmaf(v0.x, n0, ax); ay = fmaf(v0.y, n0, ay);
        az = fmaf(v0.z, n0, az); aw = fmaf(v0.w, n0, aw);
    }
    ((float4*)g_bufB)[node * 16 + c] = make_float4(ax, ay, az, aw);
}

// ---------------- final linear: out = relu(agg2 + b2) @ linW + linb -----------
__global__ __launch_bounds__(256) void k_final(
    const float* __restrict__ linW, const float* __restrict__ b2,
    const float* __restrict__ linb, float* __restrict__ out, int n)
{
    __shared__ float Ws[64 * 8];
    __shared__ float bs[64];
    __shared__ float lb[8];
    int tid = threadIdx.x;
#pragma unroll
    for (int i = tid; i < 128; i += 256) ((float4*)Ws)[i] = ((const float4*)linW)[i];
    if (tid < 16) ((float4*)bs)[tid] = ((const float4*)b2)[tid];
    if (tid < 2)  ((float4*)lb)[tid] = ((const float4*)linb)[tid];
    __syncthreads();

    int node = blockIdx.x * blockDim.x + tid;
    if (node >= n) return;

    float acc[8];
#pragma unroll
    for (int j = 0; j < 8; j++) acc[j] = lb[j];

    const float* xr = g_bufB + (size_t)node * 64;
    for (int k = 0; k < 64; k++) {
        float v = fmaxf(xr[k] + bs[k], 0.f);
        const float* wrow = &Ws[k * 8];
#pragma unroll
        for (int j = 0; j < 8; j++) acc[j] = fmaf(v, wrow[j], acc[j]);
    }
    float* op = out + (size_t)node * 8;
#pragma unroll
    for (int j = 0; j < 8; j += 4)
        *(float4*)(op + j) = make_float4(acc[j], acc[j + 1], acc[j + 2], acc[j + 3]);
}

// ---------------- host launcher ------------------------------------------------
extern "C" void kernel_launch(void* const* d_in, const int* in_sizes, int n_in,
                              void* d_out, int out_size)
{
    const float* x    = (const float*)d_in[0];
    const void*  ei   = d_in[1];
    const float* W0   = (const float*)d_in[2];
    const float* b0   = (const float*)d_in[3];
    const float* W1   = (const float*)d_in[4];
    const float* b1   = (const float*)d_in[5];
    const float* W2   = (const float*)d_in[6];
    const float* b2   = (const float*)d_in[7];
    const float* linW = (const float*)d_in[8];
    const float* linb = (const float*)d_in[9];
    float* out = (float*)d_out;

    int N = in_sizes[0] / DH;       // 50000
    int E = in_sizes[1] / 2;        // 800000

    const int T = 256;
    int gN  = (N + T - 1) / T;      // 196
    int gE  = (E + T - 1) / T;
    int gG  = (N + 63) / 64;        // 782 (gemm: 64 nodes/block)
    int gA  = (N + 15) / 16;        // 3125 (gather: 16 nodes/block)

    // ---- CSR build (reused by all 3 layers) ----
    k_detect<<<1, 1>>>((const int*)ei);
    k_zero<<<gN, T>>>(N);
    k_extract<<<gE, T>>>(ei, E);
    k_dis<<<gN, T>>>(N);
    k_scan1<<<gN, SCAN_B>>>(N);
    k_scan2<<<1, SCAN_B>>>(gN);
    k_scan3<<<gN, SCAN_B>>>(N, E);
    k_fill<<<gE, T>>>(E);

    // ---- layer 0 ----
    k_gemm64<false, false><<<gG, T>>>(x, W0, nullptr, N);
    k_gather<<<gA, T>>>(N);
    // ---- layer 1 ----
    k_gemm64<true, true><<<gG, T>>>(nullptr, W1, b0, N);
    k_gather<<<gA, T>>>(N);
    // ---- layer 2 ----
    k_gemm64<true, true><<<gG, T>>>(nullptr, W2, b1, N);
    k_gather<<<gA, T>>>(N);
    // ---- head ----
    k_final<<<gN, T>>>(linW, b2, linb, out, N);
}